// round 13
// baseline (speedup 1.0000x reference)
#include <cuda_runtime.h>

// Problem constants
#define DIMN   16
#define SECN   16
#define SUBN   16
#define EN     256
#define BATCHN 128
#define SLN    64

// Output layout (flattened reference tuple, float32)
#define OFF_TZ1  0
#define OFF_TZ2  1024
#define OFF_FWD  2048
#define OFF_EQ   18432
#define OFF_ATT  18433
#define OFF_ORTH 35841
#define OFF_PAR  35842
#define OFF_COM  35843
#define OFF_SPA  35844
#define OFF_SEC  35845
#define OFF_SUB  35846

#define NBACK 2312   // k_back grid size

// Scratch
__device__ __align__(16) float  g_syms[EN * 256];        // expm(ge)
__device__ __align__(16) float  g_u[EN * BATCHN * DIMN]; // normalized diff rows
__device__ __align__(16) float  g_Sp[SLN * 8 * 256];     // S partials [b][sp][256], fully rewritten each call
__device__ __align__(16) float  g_inv[SLN * 256];        // expm(-S)
__device__ double g_acc[8] = {0};  // 0 sparse 1 parallel 2 orth 3 commut 4 sector 5 equiv
__device__ unsigned g_done = 0;    // k_back completion counter

// ---------------------------------------------------------------------------
// f32x2 packed helpers
__device__ __forceinline__ unsigned long long pk2(float lo, float hi) {
    unsigned long long r;
    asm("mov.b64 %0, {%1, %2};" : "=l"(r) : "f"(lo), "f"(hi));
    return r;
}
__device__ __forceinline__ void upk2(float& lo, float& hi, unsigned long long v) {
    asm("mov.b64 {%0, %1}, %2;" : "=f"(lo), "=f"(hi) : "l"(v));
}
__device__ __forceinline__ unsigned long long ffma2(unsigned long long a,
                                                    unsigned long long b,
                                                    unsigned long long c) {
    unsigned long long d;
    asm("fma.rn.f32x2 %0, %1, %2, %3;" : "=l"(d) : "l"(a), "l"(b), "l"(c));
    return d;
}

// ---------------------------------------------------------------------------
// Warp-cooperative expm of one 16x16 matrix given in registers: scaling &
// squaring + order-8 Taylor Horner (theta=0.7). Lane owns half a row:
// r = lane>>1, cols [c0, c0+8), c0 = (lane&1)*8. a[8] = input elements
// (already sign-applied). Result left in res registers AND stored to dst.
__device__ __forceinline__ void warp_expm_reg(const float a[8],
                                              float* __restrict__ dst,
                                              float* bufA, float* bufB,
                                              float res[8]) {
    const int lane = threadIdx.x & 31;
    const int r = lane >> 1;
    const int c0 = (lane & 1) * 8;
    const int c0p = 8 - c0;
    const int base = lane * 8;            // == r*16 + c0

    // inf-norm: row sums then warp max
    float rs = 0.f;
    #pragma unroll
    for (int k = 0; k < 8; k++) rs += fabsf(a[k]);
    rs += __shfl_xor_sync(0xffffffffu, rs, 1);
    float mx = rs;
    #pragma unroll
    for (int off = 2; off < 32; off <<= 1)
        mx = fmaxf(mx, __shfl_xor_sync(0xffffffffu, mx, off));
    int s = 0;
    while (mx > 0.7f && s < 48) { mx *= 0.5f; s++; }

    const float sc = exp2f(-(float)s);
    float b[8], barow[16];
    #pragma unroll
    for (int k = 0; k < 8; k++) b[k] = a[k] * sc;
    #pragma unroll
    for (int k = 0; k < 8; k++) {
        barow[c0 + k] = b[k];
        res[k] = b[k] * (1.0f / 8.0f) + ((r == c0 + k) ? 1.0f : 0.0f);
    }
    #pragma unroll
    for (int k = 0; k < 8; k++)
        barow[c0p + k] = __shfl_xor_sync(0xffffffffu, b[k], 1);

    float* cur = bufA;
    float* nxt = bufB;
    #pragma unroll
    for (int k = 0; k < 8; k++) cur[base + k] = res[k];
    __syncwarp();

    // Horner: P <- B*P/kk + I, kk = 7..1
    #pragma unroll 1
    for (int kk = 7; kk >= 1; kk--) {
        float acc0 = 0.f, acc1 = 0.f, acc2 = 0.f, acc3 = 0.f;
        float acc4 = 0.f, acc5 = 0.f, acc6 = 0.f, acc7 = 0.f;
        #pragma unroll
        for (int j = 0; j < 16; j++) {
            const float av = barow[j];
            const float4 q0 = *(const float4*)(cur + j * 16 + c0);
            const float4 q1 = *(const float4*)(cur + j * 16 + c0 + 4);
            acc0 += av * q0.x; acc1 += av * q0.y; acc2 += av * q0.z; acc3 += av * q0.w;
            acc4 += av * q1.x; acc5 += av * q1.y; acc6 += av * q1.z; acc7 += av * q1.w;
        }
        const float inv = 1.0f / (float)kk;
        res[0] = acc0 * inv + ((r == c0 + 0) ? 1.f : 0.f);
        res[1] = acc1 * inv + ((r == c0 + 1) ? 1.f : 0.f);
        res[2] = acc2 * inv + ((r == c0 + 2) ? 1.f : 0.f);
        res[3] = acc3 * inv + ((r == c0 + 3) ? 1.f : 0.f);
        res[4] = acc4 * inv + ((r == c0 + 4) ? 1.f : 0.f);
        res[5] = acc5 * inv + ((r == c0 + 5) ? 1.f : 0.f);
        res[6] = acc6 * inv + ((r == c0 + 6) ? 1.f : 0.f);
        res[7] = acc7 * inv + ((r == c0 + 7) ? 1.f : 0.f);
        #pragma unroll
        for (int k = 0; k < 8; k++) nxt[base + k] = res[k];
        __syncwarp();
        float* t_ = cur; cur = nxt; nxt = t_;
    }

    // Squarings: P <- P*P.
    #pragma unroll 1
    for (int i = 0; i < s; i++) {
        float arow[16];
        #pragma unroll
        for (int k = 0; k < 8; k++) {
            arow[c0 + k] = res[k];
            arow[c0p + k] = __shfl_xor_sync(0xffffffffu, res[k], 1);
        }
        float acc0 = 0.f, acc1 = 0.f, acc2 = 0.f, acc3 = 0.f;
        float acc4 = 0.f, acc5 = 0.f, acc6 = 0.f, acc7 = 0.f;
        #pragma unroll
        for (int j = 0; j < 16; j++) {
            const float av = arow[j];
            const float4 q0 = *(const float4*)(cur + j * 16 + c0);
            const float4 q1 = *(const float4*)(cur + j * 16 + c0 + 4);
            acc0 += av * q0.x; acc1 += av * q0.y; acc2 += av * q0.z; acc3 += av * q0.w;
            acc4 += av * q1.x; acc5 += av * q1.y; acc6 += av * q1.z; acc7 += av * q1.w;
        }
        res[0] = acc0; res[1] = acc1; res[2] = acc2; res[3] = acc3;
        res[4] = acc4; res[5] = acc5; res[6] = acc6; res[7] = acc7;
        #pragma unroll
        for (int k = 0; k < 8; k++) nxt[base + k] = res[k];
        __syncwarp();
        float* t_ = cur; cur = nxt; nxt = t_;
    }

    ((float4*)dst)[lane * 2]     = make_float4(res[0], res[1], res[2], res[3]);
    ((float4*)dst)[lane * 2 + 1] = make_float4(res[4], res[5], res[6], res[7]);
}

// ---------------------------------------------------------------------------
// K1: blocks [0,32): expm(ge) 8/block + fused diff/sparse/normalize;
//     [32,152): commut pairs; [152,664): head (b,sp) + fused subsyms.
__global__ void __launch_bounds__(256) k_front(
        const float* __restrict__ ge,
        const float* __restrict__ mean, const float* __restrict__ logvar,
        const float* __restrict__ z, const float* __restrict__ lw,
        const float* __restrict__ lb, const float* __restrict__ gn,
        float* __restrict__ out) {
    __shared__ float sm[4096];
    const int tid = threadIdx.x;
    const int wid = tid >> 5;
    const int lane = tid & 31;
    const int blk = blockIdx.x;

    if (blk < 32) {
        const int m = blk * 8 + wid;
        float* bufA = sm + wid * 512;
        float* bufB = bufA + 256;
        float ain[8], res[8];
        {
            const float4 v0 = ((const float4*)(ge + m * 256))[lane * 2];
            const float4 v1 = ((const float4*)(ge + m * 256))[lane * 2 + 1];
            ain[0]=v0.x; ain[1]=v0.y; ain[2]=v0.z; ain[3]=v0.w;
            ain[4]=v1.x; ain[5]=v1.y; ain[6]=v1.z; ain[7]=v1.w;
        }
        warp_expm_reg(ain, g_syms + m * 256, bufA, bufB, res);
        // park final matrix in bufA (layout [r*16+c])
        #pragma unroll
        for (int k = 0; k < 8; k++) bufA[lane * 8 + k] = res[k];
        __syncwarp();

        // ---- fused diff: rows of z vs this sym ----
        const float* sym = bufA;
        float spsum = 0.f;
        #pragma unroll 1
        for (int p = 0; p < 2; p++) {
            const int r0 = p * 64 + lane;
            const int r1 = r0 + 32;
            float zr0[16], zr1[16], v0[16], v1[16];
            {
                const float4* zp = (const float4*)z;
                float4 t0 = zp[r0 * 4], t1 = zp[r0 * 4 + 1],
                       t2 = zp[r0 * 4 + 2], t3 = zp[r0 * 4 + 3];
                zr0[0]=t0.x; zr0[1]=t0.y; zr0[2]=t0.z; zr0[3]=t0.w;
                zr0[4]=t1.x; zr0[5]=t1.y; zr0[6]=t1.z; zr0[7]=t1.w;
                zr0[8]=t2.x; zr0[9]=t2.y; zr0[10]=t2.z; zr0[11]=t2.w;
                zr0[12]=t3.x; zr0[13]=t3.y; zr0[14]=t3.z; zr0[15]=t3.w;
                float4 u0 = zp[r1 * 4], u1 = zp[r1 * 4 + 1],
                       u2 = zp[r1 * 4 + 2], u3 = zp[r1 * 4 + 3];
                zr1[0]=u0.x; zr1[1]=u0.y; zr1[2]=u0.z; zr1[3]=u0.w;
                zr1[4]=u1.x; zr1[5]=u1.y; zr1[6]=u1.z; zr1[7]=u1.w;
                zr1[8]=u2.x; zr1[9]=u2.y; zr1[10]=u2.z; zr1[11]=u2.w;
                zr1[12]=u3.x; zr1[13]=u3.y; zr1[14]=u3.z; zr1[15]=u3.w;
            }
            #pragma unroll
            for (int d = 0; d < 16; d++) { v0[d] = 0.f; v1[d] = 0.f; }
            #pragma unroll
            for (int k = 0; k < 16; k++) {
                const float4 s0 = *(const float4*)(sym + k * 16);
                const float4 s1 = *(const float4*)(sym + k * 16 + 4);
                const float4 s2q = *(const float4*)(sym + k * 16 + 8);
                const float4 s3 = *(const float4*)(sym + k * 16 + 12);
                const float a0 = zr0[k], a1 = zr1[k];
                v0[0]+=a0*s0.x;  v0[1]+=a0*s0.y;  v0[2]+=a0*s0.z;  v0[3]+=a0*s0.w;
                v0[4]+=a0*s1.x;  v0[5]+=a0*s1.y;  v0[6]+=a0*s1.z;  v0[7]+=a0*s1.w;
                v0[8]+=a0*s2q.x; v0[9]+=a0*s2q.y; v0[10]+=a0*s2q.z; v0[11]+=a0*s2q.w;
                v0[12]+=a0*s3.x; v0[13]+=a0*s3.y; v0[14]+=a0*s3.z; v0[15]+=a0*s3.w;
                v1[0]+=a1*s0.x;  v1[1]+=a1*s0.y;  v1[2]+=a1*s0.z;  v1[3]+=a1*s0.w;
                v1[4]+=a1*s1.x;  v1[5]+=a1*s1.y;  v1[6]+=a1*s1.z;  v1[7]+=a1*s1.w;
                v1[8]+=a1*s2q.x; v1[9]+=a1*s2q.y; v1[10]+=a1*s2q.z; v1[11]+=a1*s2q.w;
                v1[12]+=a1*s3.x; v1[13]+=a1*s3.y; v1[14]+=a1*s3.z; v1[15]+=a1*s3.w;
            }
            {
                float s2 = 0.f, mxq = 0.f;
                #pragma unroll
                for (int d = 0; d < 16; d++) {
                    float val = zr0[d] - v0[d];
                    v0[d] = val;
                    float q = val * val;
                    s2 += q; mxq = fmaxf(mxq, q);
                }
                float sp = s2 - mxq; spsum += sp * sp;
                float invn = rsqrtf(s2);
                float4* du = (float4*)(g_u + (m * 128 + r0) * 16);
                du[0] = make_float4(v0[0]*invn, v0[1]*invn, v0[2]*invn, v0[3]*invn);
                du[1] = make_float4(v0[4]*invn, v0[5]*invn, v0[6]*invn, v0[7]*invn);
                du[2] = make_float4(v0[8]*invn, v0[9]*invn, v0[10]*invn, v0[11]*invn);
                du[3] = make_float4(v0[12]*invn, v0[13]*invn, v0[14]*invn, v0[15]*invn);
            }
            {
                float s2 = 0.f, mxq = 0.f;
                #pragma unroll
                for (int d = 0; d < 16; d++) {
                    float val = zr1[d] - v1[d];
                    v1[d] = val;
                    float q = val * val;
                    s2 += q; mxq = fmaxf(mxq, q);
                }
                float sp = s2 - mxq; spsum += sp * sp;
                float invn = rsqrtf(s2);
                float4* du = (float4*)(g_u + (m * 128 + r1) * 16);
                du[0] = make_float4(v1[0]*invn, v1[1]*invn, v1[2]*invn, v1[3]*invn);
                du[1] = make_float4(v1[4]*invn, v1[5]*invn, v1[6]*invn, v1[7]*invn);
                du[2] = make_float4(v1[8]*invn, v1[9]*invn, v1[10]*invn, v1[11]*invn);
                du[3] = make_float4(v1[12]*invn, v1[13]*invn, v1[14]*invn, v1[15]*invn);
            }
        }
        #pragma unroll
        for (int off = 16; off > 0; off >>= 1)
            spsum += __shfl_down_sync(0xffffffffu, spsum, off);
        if (lane == 0) atomicAdd(&g_acc[0], (double)spsum);
    } else if (blk < 152) {
        // ---- commut pair j = blk-32 ----
        float* gA  = sm;
        float* gB  = sm + 256;
        float* gCa = sm + 512;
        float* gCb = sm + 768;
        float* rwp = sm + 1024;
        const int j = blk - 32;
        int p = j;
        int a = 0;
        while (p >= 15 - a) { p -= 15 - a; a++; }
        const int b2 = a + 1 + p;
        const int r = tid >> 4, s = tid & 15;

        gA[tid] = ge[a * 256 + tid];
        gB[tid] = ge[b2 * 256 + tid];
        {
            int c = tid >> 4, ss = tid & 15;
            gCa[tid] = ge[(c * 16) * 256 + a * 16 + ss];
            gCb[tid] = ge[(c * 16) * 256 + b2 * 16 + ss];
        }
        __syncthreads();

        float R1 = 0.f, R2 = 0.f;
        #pragma unroll
        for (int cc = 0; cc < 16; cc++) {
            R1 += gA[r * 16 + cc] * gCb[cc * 16 + s];
            R2 += gB[r * 16 + cc] * gCa[cc * 16 + s];
        }
        float d = R1 - R2;
        float local = d * d;
        #pragma unroll
        for (int off = 16; off > 0; off >>= 1)
            local += __shfl_down_sync(0xffffffffu, local, off);
        if (lane == 0) rwp[wid] = local;
        __syncthreads();
        if (tid == 0) {
            float t = 0.f;
            #pragma unroll
            for (int w = 0; w < 8; w++) t += rwp[w];
            atomicAdd(&g_acc[3], (double)(2.0f * t) * (double)(120 - j));
        }
    } else {
        // ---- head: block = (b, sector-pair sp), fused subsyms ----
        float* feat  = sm;          // 64
        float* probl = sm + 64;     // 36 local rows
        float* wsm   = sm + 100;    // 32: w for the 2 sectors
        const int idx = blk - 152;
        const int b = idx >> 3, sp = idx & 7;

        if (tid < 64) {
            float v;
            if (tid < 16)       v = mean[b * 16 + tid];
            else if (tid < 32)  v = expf(0.5f * logvar[b * 16 + (tid - 16)]);
            else if (tid < 48)  v = mean[(64 + b) * 16 + (tid - 32)];
            else                v = expf(0.5f * mean[(64 + b) * 16 + (tid - 48)]);
            feat[tid] = v;
        }
        __syncthreads();

        // 36 rows: lr<4 -> sector logits rows 4sp+lr; else fprob rows 32+32sp+(lr-4)
        {
            const float f0 = feat[lane], f1 = feat[lane + 32];
            for (int lr = wid; lr < 36; lr += 8) {
                const int jj = (lr < 4) ? (4 * sp + lr) : (32 + 32 * sp + (lr - 4));
                const float* wrow = lw + jj * 64;
                float acc = wrow[lane] * f0 + wrow[lane + 32] * f1;
                acc += __shfl_down_sync(0xffffffffu, acc, 16);
                acc += __shfl_down_sync(0xffffffffu, acc, 8);
                acc += __shfl_down_sync(0xffffffffu, acc, 4);
                acc += __shfl_down_sync(0xffffffffu, acc, 2);
                acc += __shfl_down_sync(0xffffffffu, acc, 1);
                if (lane == 0) probl[lr] = acc + lb[jj];
            }
        }
        __syncthreads();

        if (tid < 2) {
            const int t = tid;
            const int s = 2 * sp + t;
            float l0 = probl[2 * t], l1 = probl[2 * t + 1];
            float m = fmaxf(l0, l1);
            float e0 = expf(l0 - m), e1 = expf(l1 - m);
            float Z = e0 + e1;
            float p0 = e0 / Z, p1 = e1 / Z;
            float mm = fmaxf(p0, p1);
            float lse = mm + logf(expf(p0 - mm) + expf(p1 - mm));
            float zd = z[b * 16 + s] - z[(64 + b) * 16 + s];
            int tgt = (fabsf(zd) > 0.2f) ? 1 : 0;
            float v = -((tgt ? p1 : p0) - lse);
            v += __shfl_down_sync(0x3u, v, 1);
            if (t == 0) atomicAdd(&g_acc[4], (double)v);

            float g0 = gn[(b * 16 + s) * 2], g1 = gn[(b * 16 + s) * 2 + 1];
            const float TAUF = 0.0001f;
            float d0 = (l0 + g0) / TAUF, d1 = (l1 + g1) / TAUF;
            float m2 = fmaxf(d0, d1);
            float a0 = expf(d0 - m2), a1 = expf(d1 - m2);
            float attn1 = a1 / (a0 + a1);
            out[OFF_ATT + b * 272 + s] = attn1;

            float mx = -1e30f;
            #pragma unroll
            for (int u = 0; u < 16; u++) mx = fmaxf(mx, probl[4 + 16 * t + u]);
            float ex[16];
            float sum = 0.f;
            #pragma unroll
            for (int u = 0; u < 16; u++) {
                ex[u] = expf(probl[4 + 16 * t + u] - mx);
                sum += ex[u];
            }
            float inv = 1.0f / sum;
            #pragma unroll
            for (int u = 0; u < 16; u++) {
                float f = ex[u] * inv;
                out[OFF_ATT + b * 272 + 16 + s * 16 + u] = f;
                wsm[t * 16 + u] = f * attn1;
            }
        }
        __syncthreads();

        // ---- fused subsyms: write per-(b,sp) S-partial (no atomics) ----
        float partial = 0.f;
        #pragma unroll
        for (int s2i = 0; s2i < 2; s2i++) {
            const int s = 2 * sp + s2i;
            float a = 0.f;
            #pragma unroll
            for (int u = 0; u < 16; u++)
                a += wsm[s2i * 16 + u] * ge[(s * 16 + u) * 256 + tid];
            out[OFF_SUB + b * 4096 + s * 256 + tid] = a;
            partial += a;
        }
        g_Sp[(b * 8 + sp) * 256 + tid] = partial;
    }
}

// ---------------------------------------------------------------------------
// K3: blocks [0,16) expm(+/-S) 8/block + fused tz + equivariant partials;
//     blocks [16,2312) gram tiles. Last-to-finish block writes scalars+resets.
__global__ void __launch_bounds__(256) k_back(const int* __restrict__ sidx,
                                              const float* __restrict__ z,
                                              float* __restrict__ out) {
    __shared__ float sm[4352];
    __shared__ int lastf;
    const int tid = threadIdx.x;

    if (blockIdx.x < 16) {
        const int wid = tid >> 5;
        const int lane = tid & 31;
        const int m = blockIdx.x * 8 + wid;     // 0..127
        const int b = m & 63;
        const bool inv = m >= 64;
        float* dst = inv ? (g_inv + b * 256) : (out + OFF_FWD + b * 256);

        // sum the 8 S-partials for batch b (fixed order -> deterministic)
        float ain[8];
        #pragma unroll
        for (int k = 0; k < 8; k++) ain[k] = 0.f;
        const float4* Sp = (const float4*)(g_Sp + b * 8 * 256);
        #pragma unroll
        for (int sp = 0; sp < 8; sp++) {
            const float4 u0 = Sp[sp * 64 + lane * 2];
            const float4 u1 = Sp[sp * 64 + lane * 2 + 1];
            ain[0] += u0.x; ain[1] += u0.y; ain[2] += u0.z; ain[3] += u0.w;
            ain[4] += u1.x; ain[5] += u1.y; ain[6] += u1.z; ain[7] += u1.w;
        }
        if (inv) {
            #pragma unroll
            for (int k = 0; k < 8; k++) ain[k] = -ain[k];
        }

        float res[8];
        warp_expm_reg(ain, dst, sm + wid * 512, sm + wid * 512 + 256, res);

        // ---- fused tz + equivariant partial ----
        const int r = lane >> 1;
        const int c0 = (lane & 1) * 8;
        const int zin = inv ? (64 + b) : b;
        const int zcm = inv ? b : (64 + b);
        const float zv = z[zin * 16 + r];
        float part[8];
        #pragma unroll
        for (int k = 0; k < 8; k++) part[k] = zv * res[k];
        #pragma unroll
        for (int off = 2; off < 32; off <<= 1) {
            #pragma unroll
            for (int k = 0; k < 8; k++)
                part[k] += __shfl_xor_sync(0xffffffffu, part[k], off);
        }
        float e = 0.f;
        if (lane < 2) {
            float* tzout = out + (inv ? OFF_TZ2 : OFF_TZ1) + b * 16 + c0;
            ((float4*)tzout)[0] = make_float4(part[0], part[1], part[2], part[3]);
            ((float4*)tzout)[1] = make_float4(part[4], part[5], part[6], part[7]);
            const float4 zc0 = *(const float4*)(z + zcm * 16 + c0);
            const float4 zc1 = *(const float4*)(z + zcm * 16 + c0 + 4);
            float d;
            d = part[0] - zc0.x; e += d * d;  d = part[1] - zc0.y; e += d * d;
            d = part[2] - zc0.z; e += d * d;  d = part[3] - zc0.w; e += d * d;
            d = part[4] - zc1.x; e += d * d;  d = part[5] - zc1.y; e += d * d;
            d = part[6] - zc1.z; e += d * d;  d = part[7] - zc1.w; e += d * d;
        }
        e += __shfl_down_sync(0xffffffffu, e, 1);
        if (lane == 0) atomicAdd(&g_acc[5], (double)e);
    } else {
        float* As  = sm;
        float* Bs  = sm + 2048;
        float* rwp = sm + 4096;
        const int bi = blockIdx.x - 16;
        const bool isOrth = bi >= 2176;

        const float* baseA;
        const float* baseB;
        float mult;
        if (!isOrth) {
            const int sec = bi / 136;
            int p = bi % 136;
            int ti = 0;
            while (p >= 16 - ti) { p -= 16 - ti; ti++; }
            const int tj = ti + p;
            baseA = g_u + (sec * 2048 + ti * 128) * 16;
            baseB = g_u + (sec * 2048 + tj * 128) * 16;
            mult = (ti == tj) ? 1.0f : 2.0f;
        } else {
            int p = bi - 2176;
            int s = 0;
            while (p >= 15 - s) { p -= 15 - s; s++; }
            const int t2 = s + 1 + p;
            baseA = g_u + (s * 16 + sidx[s]) * 2048;
            baseB = g_u + (t2 * 16 + sidx[t2]) * 2048;
            mult = 2.0f;
        }

        // Load both 128x16 tiles transposed to [k][m].
        {
            const float4* a4 = (const float4*)baseA;
            const float4* b4 = (const float4*)baseB;
            #pragma unroll
            for (int i = 0; i < 2; i++) {
                const int idx = tid * 2 + i;
                const float4 va = a4[idx];
                const float4 vb = b4[idx];
                const int m = idx >> 2;
                const int k = (idx & 3) * 4;
                As[(k + 0) * 128 + m] = va.x; As[(k + 1) * 128 + m] = va.y;
                As[(k + 2) * 128 + m] = va.z; As[(k + 3) * 128 + m] = va.w;
                Bs[(k + 0) * 128 + m] = vb.x; Bs[(k + 1) * 128 + m] = vb.y;
                Bs[(k + 2) * 128 + m] = vb.z; Bs[(k + 3) * 128 + m] = vb.w;
            }
        }
        __syncthreads();

        const int tx = tid & 15, ty = tid >> 4;
        unsigned long long acc[8][4];
        #pragma unroll
        for (int m = 0; m < 8; m++)
            #pragma unroll
            for (int n = 0; n < 4; n++) acc[m][n] = 0ULL;

        #pragma unroll
        for (int k = 0; k < 16; k++) {
            const float4 a0 = *(const float4*)(As + k * 128 + ty * 8);
            const float4 a1 = *(const float4*)(As + k * 128 + ty * 8 + 4);
            unsigned long long bp[4];
            {
                const ulonglong2 q0 = *(const ulonglong2*)(Bs + k * 128 + tx * 8);
                const ulonglong2 q1 = *(const ulonglong2*)(Bs + k * 128 + tx * 8 + 4);
                bp[0] = q0.x; bp[1] = q0.y; bp[2] = q1.x; bp[3] = q1.y;
            }
            const float av[8] = {a0.x, a0.y, a0.z, a0.w, a1.x, a1.y, a1.z, a1.w};
            #pragma unroll
            for (int m = 0; m < 8; m++) {
                const unsigned long long am = pk2(av[m], av[m]);
                #pragma unroll
                for (int n = 0; n < 4; n++) acc[m][n] = ffma2(am, bp[n], acc[m][n]);
            }
        }

        float local = 0.f;
        #pragma unroll
        for (int m = 0; m < 8; m++) {
            float l0, h0, l1, h1, l2, h2, l3, h3;
            upk2(l0, h0, acc[m][0]); upk2(l1, h1, acc[m][1]);
            upk2(l2, h2, acc[m][2]); upk2(l3, h3, acc[m][3]);
            if (isOrth) {
                local += l0 * l0 + h0 * h0 + l1 * l1 + h1 * h1
                       + l2 * l2 + h2 * h2 + l3 * l3 + h3 * h3;
            } else {
                // fuse 4 logs: factors >= 1e-9 so product >= 1e-36 > FLT_MIN
                float p0 = fmaf(l0, l0, 1e-9f) * fmaf(h0, h0, 1e-9f)
                         * fmaf(l1, l1, 1e-9f) * fmaf(h1, h1, 1e-9f);
                float p1 = fmaf(l2, l2, 1e-9f) * fmaf(h2, h2, 1e-9f)
                         * fmaf(l3, l3, 1e-9f) * fmaf(h3, h3, 1e-9f);
                local -= __logf(p0) + __logf(p1);
            }
        }
        local *= mult;

        #pragma unroll
        for (int off = 16; off > 0; off >>= 1)
            local += __shfl_down_sync(0xffffffffu, local, off);
        if ((tid & 31) == 0) rwp[tid >> 5] = local;
        __syncthreads();
        if (tid == 0) {
            float t = 0.f;
            #pragma unroll
            for (int w = 0; w < 8; w++) t += rwp[w];
            atomicAdd(&g_acc[isOrth ? 2 : 1], (double)t);
        }
    }

    // ---- completion counter; last block finalizes + resets ----
    __threadfence();
    __syncthreads();
    if (tid == 0) lastf = (atomicAdd(&g_done, 1u) == NBACK - 1u) ? 1 : 0;
    __syncthreads();
    if (!lastf) return;
    __threadfence();

    if (tid == 0) {
        out[OFF_EQ]   = (float)(g_acc[5] / 1024.0);
        out[OFF_SPA]  = (float)(g_acc[0] / 32768.0);
        out[OFF_PAR]  = (float)(g_acc[1] / 67108864.0);
        out[OFF_ORTH] = (float)(g_acc[2] / 4194304.0);
        out[OFF_COM]  = (float)(g_acc[3] / 16777216.0);
        out[OFF_SEC]  = (float)(g_acc[4] / 64.0);
        #pragma unroll
        for (int i = 0; i < 8; i++) g_acc[i] = 0.0;   // ready for next replay
        g_done = 0;
    }
}

// ---------------------------------------------------------------------------
extern "C" void kernel_launch(void* const* d_in, const int* in_sizes, int n_in,
                              void* d_out, int out_size) {
    const float* mean   = (const float*)d_in[0];
    const float* logvar = (const float*)d_in[1];
    const float* z      = (const float*)d_in[2];
    const float* ge     = (const float*)d_in[3];
    const float* lw     = (const float*)d_in[4];
    const float* lb     = (const float*)d_in[5];
    const float* gn     = (const float*)d_in[6];
    const int*   sidx   = (const int*)d_in[7];
    float* out = (float*)d_out;

    k_front<<<664, 256>>>(ge, mean, logvar, z, lw, lb, gn, out); // expm+diff, commut, head+subsyms
    k_back<<<NBACK, 256>>>(sidx, z, out);                        // expm(+/-S)+tz+gram+finalize
}

// round 14
// speedup vs baseline: 1.1083x; 1.1083x over previous
#include <cuda_runtime.h>

// Problem constants
#define DIMN   16
#define SECN   16
#define SUBN   16
#define EN     256
#define BATCHN 128
#define SLN    64

// Output layout (flattened reference tuple, float32)
#define OFF_TZ1  0
#define OFF_TZ2  1024
#define OFF_FWD  2048
#define OFF_EQ   18432
#define OFF_ATT  18433
#define OFF_ORTH 35841
#define OFF_PAR  35842
#define OFF_COM  35843
#define OFF_SPA  35844
#define OFF_SEC  35845
#define OFF_SUB  35846

// Scratch
__device__ __align__(16) float  g_syms[EN * 256];        // expm(ge) (dst only)
__device__ __align__(16) float  g_u[EN * BATCHN * DIMN]; // normalized diff rows
__device__ __align__(16) float  g_Sp[SLN * 8 * 256];     // S partials [b][sp][256], rewritten each call
__device__ __align__(16) float  g_inv[SLN * 256];        // expm(-S)
__device__ double g_acc[8] = {0};  // 0 sparse 1 parallel 2 orth 3 commut 4 sector 5 equiv

// ---------------------------------------------------------------------------
// f32x2 packed helpers
__device__ __forceinline__ void upk2(float& lo, float& hi, unsigned long long v) {
    asm("mov.b64 {%0, %1}, %2;" : "=f"(lo), "=f"(hi) : "l"(v));
}
__device__ __forceinline__ unsigned long long ffma2(unsigned long long a,
                                                    unsigned long long b,
                                                    unsigned long long c) {
    unsigned long long d;
    asm("fma.rn.f32x2 %0, %1, %2, %3;" : "=l"(d) : "l"(a), "l"(b), "l"(c));
    return d;
}

// ---------------------------------------------------------------------------
// Warp-cooperative expm of one 16x16 matrix given in registers: scaling &
// squaring + order-8 Taylor Horner (theta=0.7). Lane owns half a row:
// r = lane>>1, cols [c0, c0+8), c0 = (lane&1)*8. Result in res AND stored.
__device__ __forceinline__ void warp_expm_reg(const float a[8],
                                              float* __restrict__ dst,
                                              float* bufA, float* bufB,
                                              float res[8]) {
    const int lane = threadIdx.x & 31;
    const int r = lane >> 1;
    const int c0 = (lane & 1) * 8;
    const int c0p = 8 - c0;
    const int base = lane * 8;            // == r*16 + c0

    float rs = 0.f;
    #pragma unroll
    for (int k = 0; k < 8; k++) rs += fabsf(a[k]);
    rs += __shfl_xor_sync(0xffffffffu, rs, 1);
    float mx = rs;
    #pragma unroll
    for (int off = 2; off < 32; off <<= 1)
        mx = fmaxf(mx, __shfl_xor_sync(0xffffffffu, mx, off));
    int s = 0;
    while (mx > 0.7f && s < 48) { mx *= 0.5f; s++; }

    const float sc = exp2f(-(float)s);
    float b[8], barow[16];
    #pragma unroll
    for (int k = 0; k < 8; k++) b[k] = a[k] * sc;
    #pragma unroll
    for (int k = 0; k < 8; k++) {
        barow[c0 + k] = b[k];
        res[k] = b[k] * (1.0f / 8.0f) + ((r == c0 + k) ? 1.0f : 0.0f);
    }
    #pragma unroll
    for (int k = 0; k < 8; k++)
        barow[c0p + k] = __shfl_xor_sync(0xffffffffu, b[k], 1);

    float* cur = bufA;
    float* nxt = bufB;
    #pragma unroll
    for (int k = 0; k < 8; k++) cur[base + k] = res[k];
    __syncwarp();

    #pragma unroll 1
    for (int kk = 7; kk >= 1; kk--) {
        float acc0 = 0.f, acc1 = 0.f, acc2 = 0.f, acc3 = 0.f;
        float acc4 = 0.f, acc5 = 0.f, acc6 = 0.f, acc7 = 0.f;
        #pragma unroll
        for (int j = 0; j < 16; j++) {
            const float av = barow[j];
            const float4 q0 = *(const float4*)(cur + j * 16 + c0);
            const float4 q1 = *(const float4*)(cur + j * 16 + c0 + 4);
            acc0 += av * q0.x; acc1 += av * q0.y; acc2 += av * q0.z; acc3 += av * q0.w;
            acc4 += av * q1.x; acc5 += av * q1.y; acc6 += av * q1.z; acc7 += av * q1.w;
        }
        const float inv = 1.0f / (float)kk;
        res[0] = acc0 * inv + ((r == c0 + 0) ? 1.f : 0.f);
        res[1] = acc1 * inv + ((r == c0 + 1) ? 1.f : 0.f);
        res[2] = acc2 * inv + ((r == c0 + 2) ? 1.f : 0.f);
        res[3] = acc3 * inv + ((r == c0 + 3) ? 1.f : 0.f);
        res[4] = acc4 * inv + ((r == c0 + 4) ? 1.f : 0.f);
        res[5] = acc5 * inv + ((r == c0 + 5) ? 1.f : 0.f);
        res[6] = acc6 * inv + ((r == c0 + 6) ? 1.f : 0.f);
        res[7] = acc7 * inv + ((r == c0 + 7) ? 1.f : 0.f);
        #pragma unroll
        for (int k = 0; k < 8; k++) nxt[base + k] = res[k];
        __syncwarp();
        float* t_ = cur; cur = nxt; nxt = t_;
    }

    #pragma unroll 1
    for (int i = 0; i < s; i++) {
        float arow[16];
        #pragma unroll
        for (int k = 0; k < 8; k++) {
            arow[c0 + k] = res[k];
            arow[c0p + k] = __shfl_xor_sync(0xffffffffu, res[k], 1);
        }
        float acc0 = 0.f, acc1 = 0.f, acc2 = 0.f, acc3 = 0.f;
        float acc4 = 0.f, acc5 = 0.f, acc6 = 0.f, acc7 = 0.f;
        #pragma unroll
        for (int j = 0; j < 16; j++) {
            const float av = arow[j];
            const float4 q0 = *(const float4*)(cur + j * 16 + c0);
            const float4 q1 = *(const float4*)(cur + j * 16 + c0 + 4);
            acc0 += av * q0.x; acc1 += av * q0.y; acc2 += av * q0.z; acc3 += av * q0.w;
            acc4 += av * q1.x; acc5 += av * q1.y; acc6 += av * q1.z; acc7 += av * q1.w;
        }
        res[0] = acc0; res[1] = acc1; res[2] = acc2; res[3] = acc3;
        res[4] = acc4; res[5] = acc5; res[6] = acc6; res[7] = acc7;
        #pragma unroll
        for (int k = 0; k < 8; k++) nxt[base + k] = res[k];
        __syncwarp();
        float* t_ = cur; cur = nxt; nxt = t_;
    }

    ((float4*)dst)[lane * 2]     = make_float4(res[0], res[1], res[2], res[3]);
    ((float4*)dst)[lane * 2 + 1] = make_float4(res[4], res[5], res[6], res[7]);
}

// ---------------------------------------------------------------------------
// K1: blocks [0,256): expm(ge) (warp 0) + all-warp diff/sparse/normalize;
//     [256,376): commut pairs; [376,888): head (b,sp) + fused subsyms.
__global__ void __launch_bounds__(256) k_front(
        const float* __restrict__ ge,
        const float* __restrict__ mean, const float* __restrict__ logvar,
        const float* __restrict__ z, const float* __restrict__ lw,
        const float* __restrict__ lb, const float* __restrict__ gn,
        float* __restrict__ out) {
    __shared__ float sm[1300];
    const int tid = threadIdx.x;
    const int wid = tid >> 5;
    const int lane = tid & 31;
    const int blk = blockIdx.x;

    if (blk < 256) {
        // ---- expm(ge[blk]) by warp 0, diff by all 8 warps ----
        float* symb = sm;           // 256: final matrix [r][c]
        float* bufA = sm + 256;     // 256
        float* bufB = sm + 512;     // 256
        const int m = blk;
        if (wid == 0) {
            float ain[8], res[8];
            const float4 v0 = ((const float4*)(ge + m * 256))[lane * 2];
            const float4 v1 = ((const float4*)(ge + m * 256))[lane * 2 + 1];
            ain[0]=v0.x; ain[1]=v0.y; ain[2]=v0.z; ain[3]=v0.w;
            ain[4]=v1.x; ain[5]=v1.y; ain[6]=v1.z; ain[7]=v1.w;
            warp_expm_reg(ain, g_syms + m * 256, bufA, bufB, res);
            #pragma unroll
            for (int k = 0; k < 8; k++) symb[lane * 8 + k] = res[k];
        }
        __syncthreads();

        // each warp: 16 rows; lane handles row = wid*16 + (lane>>1), cols c0..c0+7
        const int row = wid * 16 + (lane >> 1);
        const int c0 = (lane & 1) * 8;
        float zr[16];
        {
            const float4* zp = (const float4*)(z + row * 16);
            const float4 t0 = zp[0], t1 = zp[1], t2 = zp[2], t3 = zp[3];
            zr[0]=t0.x; zr[1]=t0.y; zr[2]=t0.z; zr[3]=t0.w;
            zr[4]=t1.x; zr[5]=t1.y; zr[6]=t1.z; zr[7]=t1.w;
            zr[8]=t2.x; zr[9]=t2.y; zr[10]=t2.z; zr[11]=t2.w;
            zr[12]=t3.x; zr[13]=t3.y; zr[14]=t3.z; zr[15]=t3.w;
        }
        float v[8];
        #pragma unroll
        for (int j = 0; j < 8; j++) v[j] = 0.f;
        #pragma unroll
        for (int k = 0; k < 16; k++) {
            const float4 s0 = *(const float4*)(symb + k * 16 + c0);
            const float4 s1 = *(const float4*)(symb + k * 16 + c0 + 4);
            const float a = zr[k];
            v[0] += a * s0.x; v[1] += a * s0.y; v[2] += a * s0.z; v[3] += a * s0.w;
            v[4] += a * s1.x; v[5] += a * s1.y; v[6] += a * s1.z; v[7] += a * s1.w;
        }
        float s2h = 0.f, mxh = 0.f;
        #pragma unroll
        for (int j = 0; j < 8; j++) {
            float val = zr[c0 + j] - v[j];
            v[j] = val;
            float q = val * val;
            s2h += q; mxh = fmaxf(mxh, q);
        }
        const float s2 = s2h + __shfl_xor_sync(0xffffffffu, s2h, 1);
        const float mxq = fmaxf(mxh, __shfl_xor_sync(0xffffffffu, mxh, 1));
        float sp = s2 - mxq;
        sp = ((lane & 1) == 0) ? sp * sp : 0.f;   // count each row once
        const float invn = rsqrtf(s2);
        {
            float4* du = (float4*)(g_u + (m * 128 + row) * 16 + c0);
            du[0] = make_float4(v[0]*invn, v[1]*invn, v[2]*invn, v[3]*invn);
            du[1] = make_float4(v[4]*invn, v[5]*invn, v[6]*invn, v[7]*invn);
        }
        #pragma unroll
        for (int off = 16; off > 0; off >>= 1)
            sp += __shfl_down_sync(0xffffffffu, sp, off);
        if (lane == 0) atomicAdd(&g_acc[0], (double)sp);
    } else if (blk < 376) {
        // ---- commut pair j = blk-256 ----
        float* gA  = sm;
        float* gB  = sm + 256;
        float* gCa = sm + 512;
        float* gCb = sm + 768;
        float* rwp = sm + 1024;
        const int j = blk - 256;
        int p = j;
        int a = 0;
        while (p >= 15 - a) { p -= 15 - a; a++; }
        const int b2 = a + 1 + p;
        const int r = tid >> 4, s = tid & 15;

        gA[tid] = ge[a * 256 + tid];
        gB[tid] = ge[b2 * 256 + tid];
        {
            int c = tid >> 4, ss = tid & 15;
            gCa[tid] = ge[(c * 16) * 256 + a * 16 + ss];
            gCb[tid] = ge[(c * 16) * 256 + b2 * 16 + ss];
        }
        __syncthreads();

        float R1 = 0.f, R2 = 0.f;
        #pragma unroll
        for (int cc = 0; cc < 16; cc++) {
            R1 += gA[r * 16 + cc] * gCb[cc * 16 + s];
            R2 += gB[r * 16 + cc] * gCa[cc * 16 + s];
        }
        float d = R1 - R2;
        float local = d * d;
        #pragma unroll
        for (int off = 16; off > 0; off >>= 1)
            local += __shfl_down_sync(0xffffffffu, local, off);
        if (lane == 0) rwp[wid] = local;
        __syncthreads();
        if (tid == 0) {
            float t = 0.f;
            #pragma unroll
            for (int w = 0; w < 8; w++) t += rwp[w];
            atomicAdd(&g_acc[3], (double)(2.0f * t) * (double)(120 - j));
        }
    } else {
        // ---- head: block = (b, sector-pair sp), fused subsyms ----
        float* feat  = sm;          // 64
        float* probl = sm + 64;     // 36
        float* wsm   = sm + 100;    // 32
        const int idx = blk - 376;
        const int b = idx >> 3, sp = idx & 7;

        if (tid < 64) {
            float v;
            if (tid < 16)       v = mean[b * 16 + tid];
            else if (tid < 32)  v = expf(0.5f * logvar[b * 16 + (tid - 16)]);
            else if (tid < 48)  v = mean[(64 + b) * 16 + (tid - 32)];
            else                v = expf(0.5f * mean[(64 + b) * 16 + (tid - 48)]);
            feat[tid] = v;
        }
        __syncthreads();

        {
            const float f0 = feat[lane], f1 = feat[lane + 32];
            for (int lr = wid; lr < 36; lr += 8) {
                const int jj = (lr < 4) ? (4 * sp + lr) : (32 + 32 * sp + (lr - 4));
                const float* wrow = lw + jj * 64;
                float acc = wrow[lane] * f0 + wrow[lane + 32] * f1;
                acc += __shfl_down_sync(0xffffffffu, acc, 16);
                acc += __shfl_down_sync(0xffffffffu, acc, 8);
                acc += __shfl_down_sync(0xffffffffu, acc, 4);
                acc += __shfl_down_sync(0xffffffffu, acc, 2);
                acc += __shfl_down_sync(0xffffffffu, acc, 1);
                if (lane == 0) probl[lr] = acc + lb[jj];
            }
        }
        __syncthreads();

        if (tid < 2) {
            const int t = tid;
            const int s = 2 * sp + t;
            float l0 = probl[2 * t], l1 = probl[2 * t + 1];
            float m = fmaxf(l0, l1);
            float e0 = expf(l0 - m), e1 = expf(l1 - m);
            float Z = e0 + e1;
            float p0 = e0 / Z, p1 = e1 / Z;
            float mm = fmaxf(p0, p1);
            float lse = mm + logf(expf(p0 - mm) + expf(p1 - mm));
            float zd = z[b * 16 + s] - z[(64 + b) * 16 + s];
            int tgt = (fabsf(zd) > 0.2f) ? 1 : 0;
            float v = -((tgt ? p1 : p0) - lse);
            v += __shfl_down_sync(0x3u, v, 1);
            if (t == 0) atomicAdd(&g_acc[4], (double)v);

            float g0 = gn[(b * 16 + s) * 2], g1 = gn[(b * 16 + s) * 2 + 1];
            const float TAUF = 0.0001f;
            float d0 = (l0 + g0) / TAUF, d1 = (l1 + g1) / TAUF;
            float m2 = fmaxf(d0, d1);
            float a0 = expf(d0 - m2), a1 = expf(d1 - m2);
            float attn1 = a1 / (a0 + a1);
            out[OFF_ATT + b * 272 + s] = attn1;

            float mx = -1e30f;
            #pragma unroll
            for (int u = 0; u < 16; u++) mx = fmaxf(mx, probl[4 + 16 * t + u]);
            float ex[16];
            float sum = 0.f;
            #pragma unroll
            for (int u = 0; u < 16; u++) {
                ex[u] = expf(probl[4 + 16 * t + u] - mx);
                sum += ex[u];
            }
            float inv = 1.0f / sum;
            #pragma unroll
            for (int u = 0; u < 16; u++) {
                float f = ex[u] * inv;
                out[OFF_ATT + b * 272 + 16 + s * 16 + u] = f;
                wsm[t * 16 + u] = f * attn1;
            }
        }
        __syncthreads();

        float partial = 0.f;
        #pragma unroll
        for (int s2i = 0; s2i < 2; s2i++) {
            const int s = 2 * sp + s2i;
            float a = 0.f;
            #pragma unroll
            for (int u = 0; u < 16; u++)
                a += wsm[s2i * 16 + u] * ge[(s * 16 + u) * 256 + tid];
            out[OFF_SUB + b * 4096 + s * 256 + tid] = a;
            partial += a;
        }
        g_Sp[(b * 8 + sp) * 256 + tid] = partial;
    }
}

// ---------------------------------------------------------------------------
// K2: blocks [0,16) expm(+/-S) 8/block + fused tz + equivariant partials;
//     blocks [16,2312) gram tiles (A-tile pre-duplicated f32x2 in smem).
__global__ void __launch_bounds__(256) k_back(const int* __restrict__ sidx,
                                              const float* __restrict__ z,
                                              float* __restrict__ out) {
    __shared__ float sm[6152];
    const int tid = threadIdx.x;

    if (blockIdx.x < 16) {
        const int wid = tid >> 5;
        const int lane = tid & 31;
        const int m = blockIdx.x * 8 + wid;     // 0..127
        const int b = m & 63;
        const bool inv = m >= 64;
        float* dst = inv ? (g_inv + b * 256) : (out + OFF_FWD + b * 256);

        // sum the 8 S-partials for batch b (fixed order -> deterministic)
        float ain[8];
        #pragma unroll
        for (int k = 0; k < 8; k++) ain[k] = 0.f;
        const float4* Sp = (const float4*)(g_Sp + b * 8 * 256);
        #pragma unroll
        for (int sp = 0; sp < 8; sp++) {
            const float4 u0 = Sp[sp * 64 + lane * 2];
            const float4 u1 = Sp[sp * 64 + lane * 2 + 1];
            ain[0] += u0.x; ain[1] += u0.y; ain[2] += u0.z; ain[3] += u0.w;
            ain[4] += u1.x; ain[5] += u1.y; ain[6] += u1.z; ain[7] += u1.w;
        }
        if (inv) {
            #pragma unroll
            for (int k = 0; k < 8; k++) ain[k] = -ain[k];
        }

        float res[8];
        warp_expm_reg(ain, dst, sm + wid * 512, sm + wid * 512 + 256, res);

        // ---- fused tz + equivariant partial ----
        const int r = lane >> 1;
        const int c0 = (lane & 1) * 8;
        const int zin = inv ? (64 + b) : b;
        const int zcm = inv ? b : (64 + b);
        const float zv = z[zin * 16 + r];
        float part[8];
        #pragma unroll
        for (int k = 0; k < 8; k++) part[k] = zv * res[k];
        #pragma unroll
        for (int off = 2; off < 32; off <<= 1) {
            #pragma unroll
            for (int k = 0; k < 8; k++)
                part[k] += __shfl_xor_sync(0xffffffffu, part[k], off);
        }
        float e = 0.f;
        if (lane < 2) {
            float* tzout = out + (inv ? OFF_TZ2 : OFF_TZ1) + b * 16 + c0;
            ((float4*)tzout)[0] = make_float4(part[0], part[1], part[2], part[3]);
            ((float4*)tzout)[1] = make_float4(part[4], part[5], part[6], part[7]);
            const float4 zc0 = *(const float4*)(z + zcm * 16 + c0);
            const float4 zc1 = *(const float4*)(z + zcm * 16 + c0 + 4);
            float d;
            d = part[0] - zc0.x; e += d * d;  d = part[1] - zc0.y; e += d * d;
            d = part[2] - zc0.z; e += d * d;  d = part[3] - zc0.w; e += d * d;
            d = part[4] - zc1.x; e += d * d;  d = part[5] - zc1.y; e += d * d;
            d = part[6] - zc1.z; e += d * d;  d = part[7] - zc1.w; e += d * d;
        }
        e += __shfl_down_sync(0xffffffffu, e, 1);
        if (lane == 0) atomicAdd(&g_acc[5], (double)e);
        return;
    }

    // ---- gram tile ----
    float* As2 = sm;            // 4096 floats: [k][m] duplicated (v,v) float2
    float* Bs  = sm + 4096;     // 2048 floats: [k][m]
    float* rwp = sm + 6144;     // 8
    const int bi = blockIdx.x - 16;
    const bool isOrth = bi >= 2176;

    const float* baseA;
    const float* baseB;
    float mult;
    if (!isOrth) {
        const int sec = bi / 136;
        int p = bi % 136;
        int ti = 0;
        while (p >= 16 - ti) { p -= 16 - ti; ti++; }
        const int tj = ti + p;
        baseA = g_u + (sec * 2048 + ti * 128) * 16;
        baseB = g_u + (sec * 2048 + tj * 128) * 16;
        mult = (ti == tj) ? 1.0f : 2.0f;
    } else {
        int p = bi - 2176;
        int s = 0;
        while (p >= 15 - s) { p -= 15 - s; s++; }
        const int t2 = s + 1 + p;
        baseA = g_u + (s * 16 + sidx[s]) * 2048;
        baseB = g_u + (t2 * 16 + sidx[t2]) * 2048;
        mult = 2.0f;
    }

    // Load tiles transposed to [k][m]; A duplicated as (v,v) pairs.
    {
        const float4* a4 = (const float4*)baseA;
        const float4* b4 = (const float4*)baseB;
        float2* Ad = (float2*)As2;
        #pragma unroll
        for (int i = 0; i < 2; i++) {
            const int idx = tid * 2 + i;
            const float4 va = a4[idx];
            const float4 vb = b4[idx];
            const int m = idx >> 2;
            const int k = (idx & 3) * 4;
            Ad[(k + 0) * 128 + m] = make_float2(va.x, va.x);
            Ad[(k + 1) * 128 + m] = make_float2(va.y, va.y);
            Ad[(k + 2) * 128 + m] = make_float2(va.z, va.z);
            Ad[(k + 3) * 128 + m] = make_float2(va.w, va.w);
            Bs[(k + 0) * 128 + m] = vb.x; Bs[(k + 1) * 128 + m] = vb.y;
            Bs[(k + 2) * 128 + m] = vb.z; Bs[(k + 3) * 128 + m] = vb.w;
        }
    }
    __syncthreads();

    const int tx = tid & 15, ty = tid >> 4;
    unsigned long long acc[8][4];
    #pragma unroll
    for (int m = 0; m < 8; m++)
        #pragma unroll
        for (int n = 0; n < 4; n++) acc[m][n] = 0ULL;

    const ulonglong2* A2 = (const ulonglong2*)As2;
    const ulonglong2* B2 = (const ulonglong2*)Bs;
    #pragma unroll
    for (int k = 0; k < 16; k++) {
        // am: 4 x LDS.128 of pre-duplicated pairs -> 8 packed broadcasts
        const ulonglong2 p0 = A2[k * 64 + ty * 4];
        const ulonglong2 p1 = A2[k * 64 + ty * 4 + 1];
        const ulonglong2 p2 = A2[k * 64 + ty * 4 + 2];
        const ulonglong2 p3 = A2[k * 64 + ty * 4 + 3];
        const unsigned long long am[8] = {p0.x, p0.y, p1.x, p1.y,
                                          p2.x, p2.y, p3.x, p3.y};
        const ulonglong2 q0 = B2[k * 32 + tx * 2];
        const ulonglong2 q1 = B2[k * 32 + tx * 2 + 1];
        const unsigned long long bp[4] = {q0.x, q0.y, q1.x, q1.y};
        #pragma unroll
        for (int m = 0; m < 8; m++) {
            #pragma unroll
            for (int n = 0; n < 4; n++) acc[m][n] = ffma2(am[m], bp[n], acc[m][n]);
        }
    }

    float local = 0.f;
    #pragma unroll
    for (int m = 0; m < 8; m++) {
        float l0, h0, l1, h1, l2, h2, l3, h3;
        upk2(l0, h0, acc[m][0]); upk2(l1, h1, acc[m][1]);
        upk2(l2, h2, acc[m][2]); upk2(l3, h3, acc[m][3]);
        if (isOrth) {
            local += l0 * l0 + h0 * h0 + l1 * l1 + h1 * h1
                   + l2 * l2 + h2 * h2 + l3 * l3 + h3 * h3;
        } else {
            // fuse 4 logs: factors >= 1e-9 so product >= 1e-36 > FLT_MIN
            float p0 = fmaf(l0, l0, 1e-9f) * fmaf(h0, h0, 1e-9f)
                     * fmaf(l1, l1, 1e-9f) * fmaf(h1, h1, 1e-9f);
            float p1 = fmaf(l2, l2, 1e-9f) * fmaf(h2, h2, 1e-9f)
                     * fmaf(l3, l3, 1e-9f) * fmaf(h3, h3, 1e-9f);
            local -= __logf(p0) + __logf(p1);
        }
    }
    local *= mult;

    #pragma unroll
    for (int off = 16; off > 0; off >>= 1)
        local += __shfl_down_sync(0xffffffffu, local, off);
    if ((tid & 31) == 0) rwp[tid >> 5] = local;
    __syncthreads();
    if (tid == 0) {
        float t = 0.f;
        #pragma unroll
        for (int w = 0; w < 8; w++) t += rwp[w];
        atomicAdd(&g_acc[isOrth ? 2 : 1], (double)t);
    }
}

// ---------------------------------------------------------------------------
// K3: scalar finalize (reads g_acc, writes 6 scalars, resets).
__global__ void k_tail(float* __restrict__ out) {
    if (threadIdx.x == 0) {
        out[OFF_EQ]   = (float)(g_acc[5] / 1024.0);
        out[OFF_SPA]  = (float)(g_acc[0] / 32768.0);
        out[OFF_PAR]  = (float)(g_acc[1] / 67108864.0);
        out[OFF_ORTH] = (float)(g_acc[2] / 4194304.0);
        out[OFF_COM]  = (float)(g_acc[3] / 16777216.0);
        out[OFF_SEC]  = (float)(g_acc[4] / 64.0);
        #pragma unroll
        for (int i = 0; i < 8; i++) g_acc[i] = 0.0;   // ready for next replay
    }
}

// ---------------------------------------------------------------------------
extern "C" void kernel_launch(void* const* d_in, const int* in_sizes, int n_in,
                              void* d_out, int out_size) {
    const float* mean   = (const float*)d_in[0];
    const float* logvar = (const float*)d_in[1];
    const float* z      = (const float*)d_in[2];
    const float* ge     = (const float*)d_in[3];
    const float* lw     = (const float*)d_in[4];
    const float* lb     = (const float*)d_in[5];
    const float* gn     = (const float*)d_in[6];
    const int*   sidx   = (const int*)d_in[7];
    float* out = (float*)d_out;

    k_front<<<888, 256>>>(ge, mean, logvar, z, lw, lb, gn, out); // expm+diff, commut, head+subsyms
    k_back<<<2312, 256>>>(sidx, z, out);                         // expm(+/-S)+tz+gram
    k_tail<<<1, 32>>>(out);                                      // scalars+reset
}